// round 17
// baseline (speedup 1.0000x reference)
#include <cuda_runtime.h>
#include <cuda_fp16.h>
#include <cstdint>
#include <math.h>

#define BB 64
#define LL 512
#define DD 768

// ---------------------------------------------------------------------------
// Scratch (device globals)
// ---------------------------------------------------------------------------
__device__ __half g_ph[(size_t)BB * LL * DD];   // normalized p, fp16
__device__ __half g_qh[(size_t)BB * LL * DD];   // normalized q, fp16
__device__ __half g_pf[(size_t)BB * LL * DD];   // raw p, fp16
__device__ __half g_qf[(size_t)BB * LL * DD];   // raw q, fp16
__device__ __half g_Ef[(size_t)BB * LL * LL];   // exp(att), fp16
__device__ float g_rsum[BB * LL];
__device__ float g_csum[BB * LL];
__device__ float g_rinv[BB * LL];
__device__ float g_cinv[BB * LL];

// ---------------------------------------------------------------------------
// Helpers
// ---------------------------------------------------------------------------
__device__ __forceinline__ uint32_t smem_u32(const void* p) {
    uint32_t a;
    asm("{ .reg .u64 t; cvta.to.shared.u64 t, %1; cvt.u32.u64 %0, t; }"
        : "=r"(a) : "l"(p));
    return a;
}
#define CP_ASYNC(dst, src) \
    asm volatile("cp.async.cg.shared.global [%0], [%1], 16;" :: "r"(dst), "l"(src))
#define CP_COMMIT() asm volatile("cp.async.commit_group;")
#define CP_WAIT1()  asm volatile("cp.async.wait_group 1;")
#define CP_WAIT2()  asm volatile("cp.async.wait_group 2;")
#define CP_WAIT0()  asm volatile("cp.async.wait_group 0;")

__device__ __forceinline__ void mma16816f(float* c, const uint32_t* a, const uint32_t* b) {
    asm volatile("mma.sync.aligned.m16n8k16.row.col.f32.f16.f16.f32 "
                 "{%0,%1,%2,%3}, {%4,%5,%6,%7}, {%8,%9}, {%0,%1,%2,%3};"
                 : "+f"(c[0]), "+f"(c[1]), "+f"(c[2]), "+f"(c[3])
                 : "r"(a[0]), "r"(a[1]), "r"(a[2]), "r"(a[3]), "r"(b[0]), "r"(b[1]));
}
__device__ __forceinline__ uint32_t packh2(float x, float y) {
    __half2 h = __floats2half2_rn(x, y);
    return *(uint32_t*)&h;
}
__device__ __forceinline__ uint32_t packhh(__half a, __half b) {
    __half2 h = __halves2half2(a, b);
    return *(uint32_t*)&h;
}

// ---------------------------------------------------------------------------
__global__ void inv_sums() {
    int i = blockIdx.x * blockDim.x + threadIdx.x;
    g_rinv[i] = 1.f / g_rsum[i];
    g_cinv[i] = 1.f / g_csum[i];
}

// ---------------------------------------------------------------------------
// Fused: L2-normalize rows -> fp16 normalized + fp16 raw copies. 1 warp/row.
// Also zeroes the atomic sum accumulators (first 32768 threads).
// ---------------------------------------------------------------------------
__global__ void normsplit_kernel(const float* __restrict__ p,
                                 const float* __restrict__ q) {
    int gid = blockIdx.x * blockDim.x + threadIdx.x;
    if (gid < BB * LL) { g_rsum[gid] = 0.f; g_csum[gid] = 0.f; }
    int warp = gid >> 5;
    int lane = threadIdx.x & 31;
    if (warp >= 2 * BB * LL) return;
    const float* src; __half *dstn, *dstr; int r;
    if (warp < BB * LL) { src = p; dstn = g_ph; dstr = g_pf; r = warp; }
    else                { src = q; dstn = g_qh; dstr = g_qf; r = warp - BB * LL; }
    const float4* row = (const float4*)(src + (size_t)r * DD);
    float4 v[6];
    float s = 0.f;
#pragma unroll
    for (int i = 0; i < 6; i++) {
        v[i] = row[lane + i * 32];
        s += v[i].x * v[i].x + v[i].y * v[i].y + v[i].z * v[i].z + v[i].w * v[i].w;
    }
#pragma unroll
    for (int o = 16; o; o >>= 1) s += __shfl_xor_sync(0xffffffffu, s, o);
    float inv = 1.f / fmaxf(sqrtf(s), 1e-8f);
    size_t base = (size_t)r * DD;
#pragma unroll
    for (int i = 0; i < 6; i++) {
        size_t e = base + 4 * (lane + i * 32);
        uint2 hn = make_uint2(packh2(v[i].x * inv, v[i].y * inv),
                              packh2(v[i].z * inv, v[i].w * inv));
        uint2 hr = make_uint2(packh2(v[i].x, v[i].y),
                              packh2(v[i].z, v[i].w));
        *(uint2*)(dstn + e) = hn;
        *(uint2*)(dstr + e) = hr;
    }
}

// ---------------------------------------------------------------------------
// HMMA att (fp16, proven R15): E = exp(phat . qhat^T)
// BM=128, BN=128, BK=32, 2-stage. 8 warps 2(m) x 4(n), warp 64x32.
// ---------------------------------------------------------------------------
#define ATT_STG 20480
#define ATT_BOFF 10240

__global__ __launch_bounds__(256, 2)
void att_hmma_kernel() {
    __shared__ __align__(128) char smc[2 * ATT_STG];

    int b = blockIdx.z;
    int m0 = blockIdx.y * 128, n0 = blockIdx.x * 128;
    const __half* Ph = g_ph + (size_t)b * LL * DD;
    const __half* Qh = g_qh + (size_t)b * LL * DD;

    uint32_t sb = smem_u32(smc);
    int t = threadIdx.x, wid = t >> 5, lane = t & 31;
    int wm = (wid >> 2) * 64, wn = (wid & 3) * 32;
    int r4 = lane >> 2, c4 = lane & 3;

    float acc[4][4][4];
#pragma unroll
    for (int i = 0; i < 4; i++)
#pragma unroll
        for (int j = 0; j < 4; j++)
#pragma unroll
            for (int k = 0; k < 4; k++) acc[i][j][k] = 0.f;

    auto LOAD = [&](int st, int k0) {
        uint32_t base = sb + (uint32_t)st * ATT_STG;
#pragma unroll
        for (int u = 0; u < 2; u++) {
            int c = t * 2 + u, row = c >> 2, cc = c & 3;
            CP_ASYNC(base + row * 80 + cc * 16,
                     Ph + (size_t)(m0 + row) * DD + k0 + cc * 8);
            CP_ASYNC(base + ATT_BOFF + row * 80 + cc * 16,
                     Qh + (size_t)(n0 + row) * DD + k0 + cc * 8);
        }
    };

    LOAD(0, 0);
    CP_COMMIT();

    const int NIT = DD / 32;   // 24
    for (int it = 0; it < NIT; it++) {
        if (it + 1 < NIT) { LOAD((it + 1) & 1, (it + 1) * 32); CP_COMMIT(); CP_WAIT1(); }
        else              { CP_WAIT0(); }
        __syncthreads();

        const uint32_t* At = (const uint32_t*)(smc + (it & 1) * ATT_STG);  // pitch 20 words
        const uint32_t* Bt = At + 2560;

#pragma unroll
        for (int s = 0; s < 2; s++) {
            uint32_t aHi[4][4], bHi[4][2];
#pragma unroll
            for (int i = 0; i < 4; i++) {
                int r0 = (wm + i * 16 + r4) * 20;
                aHi[i][0] = At[r0 + 8 * s + c4];
                aHi[i][1] = At[r0 + 160 + 8 * s + c4];
                aHi[i][2] = At[r0 + 8 * s + c4 + 4];
                aHi[i][3] = At[r0 + 160 + 8 * s + c4 + 4];
            }
#pragma unroll
            for (int j = 0; j < 4; j++) {
                int n = (wn + j * 8 + r4) * 20;
                bHi[j][0] = Bt[n + 8 * s + c4];
                bHi[j][1] = Bt[n + 8 * s + c4 + 4];
            }
#pragma unroll
            for (int i = 0; i < 4; i++)
#pragma unroll
                for (int j = 0; j < 4; j++)
                    mma16816f(acc[i][j], aHi[i], bHi[j]);
        }
        __syncthreads();
    }

    // Epilogue: exp -> fp16 store; sums from the rounded values
#pragma unroll
    for (int i = 0; i < 4; i++)
#pragma unroll
        for (int half = 0; half < 2; half++) {
            int gi = m0 + wm + i * 16 + r4 + half * 8;
            size_t base = ((size_t)b * LL + gi) * LL;
#pragma unroll
            for (int j = 0; j < 4; j++) {
                int col = n0 + wn + j * 8 + c4 * 2;
                __half2 h = __floats2half2_rn(__expf(acc[i][j][half * 2 + 0]),
                                              __expf(acc[i][j][half * 2 + 1]));
                *(uint32_t*)(g_Ef + base + col) = *(uint32_t*)&h;
                float2 hv = __half22float2(h);
                acc[i][j][half * 2 + 0] = hv.x;
                acc[i][j][half * 2 + 1] = hv.y;
            }
        }

    // Row partial sums
#pragma unroll
    for (int i = 0; i < 4; i++)
#pragma unroll
        for (int half = 0; half < 2; half++) {
            float s = 0.f;
#pragma unroll
            for (int j = 0; j < 4; j++)
                s += acc[i][j][half * 2 + 0] + acc[i][j][half * 2 + 1];
            s += __shfl_xor_sync(0xffffffffu, s, 1);
            s += __shfl_xor_sync(0xffffffffu, s, 2);
            if (c4 == 0) {
                int gi = m0 + wm + i * 16 + r4 + half * 8;
                atomicAdd(&g_rsum[b * LL + gi], s);
            }
        }

    // Col partial sums
#pragma unroll
    for (int j = 0; j < 4; j++)
#pragma unroll
        for (int z = 0; z < 2; z++) {
            float s = 0.f;
#pragma unroll
            for (int i = 0; i < 4; i++)
                s += acc[i][j][z] + acc[i][j][2 + z];
            s += __shfl_xor_sync(0xffffffffu, s, 4);
            s += __shfl_xor_sync(0xffffffffu, s, 8);
            s += __shfl_xor_sync(0xffffffffu, s, 16);
            if (r4 == 0)
                atomicAdd(&g_csum[b * LL + n0 + wn + j * 8 + c4 * 2 + z], s);
        }
}

// ---------------------------------------------------------------------------
// FUSED output GEMMs (fp16): BN 64->128 (halves E L2 re-reads), BK=16,
// 3-stage pipeline. 8 warps as 4(m) x 2(n), warp tile 32x128 (j=0..7).
//   out_p[m,n] = rinv[m] * sum_k E[m,k] * q[k,n]
//   out_q[m,n] = sum_k (E[m,k]*cinv[k]) * p[k,n]
// Stage: E 128x48B = 6144, Bq 16x272B = 4352 @6144, Bp @10496 -> 14848.
// 3 stages = 44544; cinv 3x64 @44544. Total 44736 B static smem.
// ---------------------------------------------------------------------------
#define FO_BQ 6144
#define FO_BP 10496
#define FO_STG 14848
#define FO_CINV 44544

__global__ __launch_bounds__(256)
void out_fused_kernel(float* __restrict__ OutP, float* __restrict__ OutQ) {
    __shared__ __align__(128) char smc[44736];

    int b = blockIdx.z;
    int m0 = blockIdx.y * 128, n0 = blockIdx.x * 128;
    const __half* Ef = g_Ef + (size_t)b * LL * LL;
    const __half* Qb = g_qf + (size_t)b * LL * DD;
    const __half* Pb = g_pf + (size_t)b * LL * DD;
    const float* cv = g_cinv + b * LL;

    uint32_t sb = smem_u32(smc);
    int t = threadIdx.x, wid = t >> 5, lane = t & 31;
    int wm = (wid >> 1) * 32, wn = (wid & 1) * 64;
    int r4 = lane >> 2, c4 = lane & 3;

    float accP[2][8][4], accQ[2][8][4];
#pragma unroll
    for (int i = 0; i < 2; i++)
#pragma unroll
        for (int j = 0; j < 8; j++)
#pragma unroll
            for (int k = 0; k < 4; k++) { accP[i][j][k] = 0.f; accQ[i][j][k] = 0.f; }

    // E: 128 rows x 2 chunks = 256 -> 1/thread (row = t>>1, cc = t&1).
    // Bq/Bp: 16 rows x 16 chunks = 256 each -> 1 of each per thread.
    int erow = t >> 1, ecc = t & 1;
    int brow = t >> 4, bcc = t & 15;
    auto LOAD = [&](int st, int k0) {
        uint32_t base = sb + (uint32_t)st * FO_STG;
        CP_ASYNC(base + erow * 48 + ecc * 16,
                 Ef + (size_t)(m0 + erow) * LL + k0 + ecc * 8);
        CP_ASYNC(base + FO_BQ + brow * 272 + bcc * 16,
                 Qb + (size_t)(k0 + brow) * DD + n0 + bcc * 8);
        CP_ASYNC(base + FO_BP + brow * 272 + bcc * 16,
                 Pb + (size_t)(k0 + brow) * DD + n0 + bcc * 8);
        if (t < 4)
            CP_ASYNC(sb + FO_CINV + (uint32_t)st * 64 + t * 16, cv + k0 + t * 4);
    };

    LOAD(0, 0);  CP_COMMIT();
    LOAD(1, 16); CP_COMMIT();

    const int NIT = LL / 16;   // 32
    for (int it = 0; it < NIT; it++) {
        if (it + 2 < NIT) LOAD((it + 2) % 3, (it + 2) * 16);
        CP_COMMIT();
        CP_WAIT2();
        __syncthreads();

        const uint32_t* At = (const uint32_t*)(smc + (it % 3) * FO_STG);       // pitch 12 words
        const __half* Btq = (const __half*)(smc + (it % 3) * FO_STG + FO_BQ);  // [16][136]
        const __half* Btp = (const __half*)(smc + (it % 3) * FO_STG + FO_BP);  // [16][136]
        const float* Cs = (const float*)(smc + FO_CINV + (it % 3) * 64);       // [16]

        float c0v = Cs[2 * c4],     c1v = Cs[2 * c4 + 1];
        float c8v = Cs[2 * c4 + 8], c9v = Cs[2 * c4 + 9];

        uint32_t aE[2][4];
#pragma unroll
        for (int i = 0; i < 2; i++) {
            int r0 = (wm + i * 16 + r4) * 12, r1 = r0 + 96;
            aE[i][0] = At[r0 + c4];     aE[i][1] = At[r1 + c4];
            aE[i][2] = At[r0 + c4 + 4]; aE[i][3] = At[r1 + c4 + 4];
        }

        uint32_t bq[8][2], bp[8][2];
#pragma unroll
        for (int j = 0; j < 8; j++) {
            int n = wn + j * 8 + r4;
            bq[j][0] = packhh(Btq[(2 * c4) * 136 + n],     Btq[(2 * c4 + 1) * 136 + n]);
            bq[j][1] = packhh(Btq[(2 * c4 + 8) * 136 + n], Btq[(2 * c4 + 9) * 136 + n]);
            bp[j][0] = packh2(__half2float(Btp[(2 * c4) * 136 + n]) * c0v,
                              __half2float(Btp[(2 * c4 + 1) * 136 + n]) * c1v);
            bp[j][1] = packh2(__half2float(Btp[(2 * c4 + 8) * 136 + n]) * c8v,
                              __half2float(Btp[(2 * c4 + 9) * 136 + n]) * c9v);
        }
#pragma unroll
        for (int i = 0; i < 2; i++)
#pragma unroll
            for (int j = 0; j < 8; j++) {
                mma16816f(accP[i][j], aE[i], bq[j]);
                mma16816f(accQ[i][j], aE[i], bp[j]);
            }
        __syncthreads();
    }

    // Epilogue: both outputs
#pragma unroll
    for (int i = 0; i < 2; i++)
#pragma unroll
        for (int half = 0; half < 2; half++) {
            int gi = m0 + wm + i * 16 + r4 + half * 8;
            float rs = g_rinv[b * LL + gi];
            size_t base = ((size_t)b * LL + gi) * DD;
#pragma unroll
            for (int j = 0; j < 8; j++) {
                int col = n0 + wn + j * 8 + c4 * 2;
                float2 vp, vq;
                vp.x = accP[i][j][half * 2 + 0] * rs;
                vp.y = accP[i][j][half * 2 + 1] * rs;
                vq.x = accQ[i][j][half * 2 + 0];
                vq.y = accQ[i][j][half * 2 + 1];
                *(float2*)(OutP + base + col) = vp;
                *(float2*)(OutQ + base + col) = vq;
            }
        }
}

// ---------------------------------------------------------------------------
extern "C" void kernel_launch(void* const* d_in, const int* in_sizes, int n_in,
                              void* d_out, int out_size) {
    const float* p = (const float*)d_in[0];
    const float* q = (const float*)d_in[1];
    float* out = (float*)d_out;
    float* out_p = out;
    float* out_q = out + (size_t)BB * LL * DD;

    normsplit_kernel<<<(2 * BB * LL) / 8, 256>>>(p, q);

    att_hmma_kernel<<<dim3(LL / 128, LL / 128, BB), 256>>>();

    inv_sums<<<(BB * LL) / 256, 256>>>();

    out_fused_kernel<<<dim3(DD / 128, LL / 128, BB), 256>>>(out_p, out_q);
}